// round 10
// baseline (speedup 1.0000x reference)
#include <cuda_runtime.h>
#include <stdint.h>
#include <math.h>

#define BB 4
#define TT 4096
#define CC 1024
#define HH 128
#define NQT 64

// projection scratch, tf32 bit patterns, h-dim PERMUTED per tensor:
//  g_q/g_k: perm16: c -> (c&~15)|((c&3)<<2)|(((c>>3)&1)<<1)|((c>>2)&1)
//  g_v:     permV:  c -> (c&~15)|((c&7)<<1)|((c>>3)&1)
// q pre-scaled by H^-0.5*log2(e)
__device__ uint32_t g_q[BB * TT * HH];
__device__ uint32_t g_k[BB * TT * HH];
__device__ uint32_t g_v[BB * TT * HH];

__device__ __forceinline__ uint32_t f2tf(float x) {
    uint32_t r;
    asm("cvt.rna.tf32.f32 %0, %1;" : "=r"(r) : "f"(x));
    return r;
}

// perm16 low-4 bits: swap 2-bit halves (involution)
__device__ __forceinline__ int perm16(int c) {
    return (c & ~15) | ((c & 3) << 2) | ((c >> 2) & 3);
}
__device__ __forceinline__ int permV(int c) {
    return (c & ~15) | ((c & 7) << 1) | ((c >> 3) & 1);
}

__device__ __forceinline__ void mma8(float c[4],
                                     uint32_t a0, uint32_t a1, uint32_t a2, uint32_t a3,
                                     uint32_t b0, uint32_t b1)
{
    asm volatile(
        "mma.sync.aligned.m16n8k8.row.col.f32.tf32.tf32.f32 "
        "{%0,%1,%2,%3},{%4,%5,%6,%7},{%8,%9},{%0,%1,%2,%3};"
        : "+f"(c[0]), "+f"(c[1]), "+f"(c[2]), "+f"(c[3])
        : "r"(a0), "r"(a1), "r"(a2), "r"(a3), "r"(b0), "r"(b1));
}

__device__ __forceinline__ void cp16(uint32_t dst, const void* src) {
    asm volatile("cp.async.cg.shared.global [%0], [%1], 16;"
                 :: "r"(dst), "l"(src));
}

// ---------------------------------------------------------------------------
// Projection: y = x @ W via tf32 mma. M=16384, K=1024, N=128.
// Mainloop unchanged; epilogue stages permuted values in smem, then writes
// GMEM fully coalesced (uint4). Bit-identical values vs R6.
// ---------------------------------------------------------------------------
#define PXS 4608   // 128*36 floats per X stage
#define PWS 4352   // 32*136 floats per W stage
#define PES 132    // epilogue staging row stride (128 rows x 132)

__global__ void __launch_bounds__(256, 2) proj_kernel(
    const float* __restrict__ x,
    const float* __restrict__ Wk,
    const float* __restrict__ Wq,
    const float* __restrict__ Wv)
{
    extern __shared__ float psm[];

    const int z = blockIdx.y;
    const float* W = (z == 0) ? Wq : (z == 1) ? Wk : Wv;
    uint32_t* y    = (z == 0) ? g_q : (z == 1) ? g_k : g_v;
    const float oscale = (z == 0) ? (0.08838834764831845f * 1.4426950408889634f) : 1.0f;
    const bool isV = (z == 2);

    const int row0 = blockIdx.x * 128;
    const int tid  = threadIdx.x;
    const int wid  = tid >> 5, lane = tid & 31;
    const int wm   = (wid >> 1) * 32, wn = (wid & 1) * 64;
    const int g    = lane >> 2, t = lane & 3;

    uint32_t smb = (uint32_t)__cvta_generic_to_shared((void*)psm);

    float acc[2][8][4];
#pragma unroll
    for (int i = 0; i < 2; i++)
#pragma unroll
        for (int j = 0; j < 8; j++)
#pragma unroll
            for (int q = 0; q < 4; q++) acc[i][j][q] = 0.f;

    {
        const uint32_t xd = smb;
        const uint32_t wd = smb + 2 * PXS * 4;
#pragma unroll
        for (int u = 0; u < 4; u++) {
            int v = tid + u * 256;
            int rx = v >> 3, cx = (v & 7) << 2;
            cp16(xd + (uint32_t)(rx * 36 + cx) * 4,
                 &x[(size_t)(row0 + rx) * CC + cx]);
            int rw = v >> 5, cw = (v & 31) << 2;
            cp16(wd + (uint32_t)(rw * 136 + cw) * 4,
                 &W[(size_t)rw * HH + cw]);
        }
        asm volatile("cp.async.commit_group;");
    }

    for (int k0 = 0; k0 < CC; k0 += 32) {
        asm volatile("cp.async.wait_group 0;");
        __syncthreads();

        const int st = (k0 >> 5) & 1;
        if (k0 + 32 < CC) {
            const int sn = st ^ 1;
            const uint32_t xd = smb + (uint32_t)(sn * PXS) * 4;
            const uint32_t wd = smb + (uint32_t)(2 * PXS + sn * PWS) * 4;
#pragma unroll
            for (int u = 0; u < 4; u++) {
                int v = tid + u * 256;
                int rx = v >> 3, cx = (v & 7) << 2;
                cp16(xd + (uint32_t)(rx * 36 + cx) * 4,
                     &x[(size_t)(row0 + rx) * CC + k0 + 32 + cx]);
                int rw = v >> 5, cw = (v & 31) << 2;
                cp16(wd + (uint32_t)(rw * 136 + cw) * 4,
                     &W[(size_t)(k0 + 32 + rw) * HH + cw]);
            }
            asm volatile("cp.async.commit_group;");
        }

        const float* Xs = psm + st * PXS;
        const float* Ws = psm + 2 * PXS + st * PWS;

#pragma unroll
        for (int ks = 0; ks < 32; ks += 8) {
            uint32_t a[2][4], bfr[8][2];
#pragma unroll
            for (int i = 0; i < 2; i++) {
                int r = wm + i * 16;
                a[i][0] = f2tf(Xs[(r + g) * 36 + ks + t]);
                a[i][1] = f2tf(Xs[(r + g + 8) * 36 + ks + t]);
                a[i][2] = f2tf(Xs[(r + g) * 36 + ks + t + 4]);
                a[i][3] = f2tf(Xs[(r + g + 8) * 36 + ks + t + 4]);
            }
#pragma unroll
            for (int j = 0; j < 8; j++) {
                int c = wn + j * 8 + g;
                bfr[j][0] = f2tf(Ws[(ks + t) * 136 + c]);
                bfr[j][1] = f2tf(Ws[(ks + t + 4) * 136 + c]);
            }
#pragma unroll
            for (int i = 0; i < 2; i++)
#pragma unroll
                for (int j = 0; j < 8; j++)
                    mma8(acc[i][j], a[i][0], a[i][1], a[i][2], a[i][3],
                         bfr[j][0], bfr[j][1]);
        }
    }

    // ---- epilogue: permuted scatter into smem, then coalesced STG.128 ----
    __syncthreads();   // all warps done reading pipeline stages
    uint32_t* Ss = (uint32_t*)psm;   // [128][PES]
#pragma unroll
    for (int i = 0; i < 2; i++) {
        int rlo = wm + i * 16 + g;
        int rhi = rlo + 8;
#pragma unroll
        for (int j = 0; j < 8; j++) {
            int c0 = wn + j * 8 + 2 * t;
            int c1 = c0 + 1;
            int p0 = isV ? permV(c0) : perm16(c0);
            int p1 = isV ? permV(c1) : perm16(c1);
            Ss[rlo * PES + p0] = f2tf(acc[i][j][0] * oscale);
            Ss[rlo * PES + p1] = f2tf(acc[i][j][1] * oscale);
            Ss[rhi * PES + p0] = f2tf(acc[i][j][2] * oscale);
            Ss[rhi * PES + p1] = f2tf(acc[i][j][3] * oscale);
        }
    }
    __syncthreads();
#pragma unroll
    for (int u = 0; u < 16; u++) {
        int v = tid + u * 256;
        int rr = v >> 5, c4 = (v & 31) << 2;
        *(uint4*)&y[(size_t)(row0 + rr) * HH + c4] =
            *(const uint4*)&Ss[rr * PES + c4];
    }
}

// ---------------------------------------------------------------------------
// Flash attention (causal), tf32 mma, BM=64, BN=32, 128 threads (4 warps).
// EXACT R6 structure (best measured): K/V fragments via LDS.64 (permuted
// layouts), rescale every iter, P via STS.32, single barrier per k-tile.
// ---------------------------------------------------------------------------
#define SK 136
#define SV 136
#define SP 36
#define KBUF (32 * SK)
#define VBUF (32 * SV)

__global__ void __launch_bounds__(128, 2) attn_kernel(float* __restrict__ out)
{
    extern __shared__ uint32_t smattn[];
    uint32_t* Ks = smattn;              // 2 x [32][136]
    uint32_t* Vs = Ks + 2 * KBUF;       // 2 x [32][136]
    uint32_t* Ps = Vs + 2 * VBUF;       // [64][36]

    // balanced schedule: pair bid s with s+148 (same SM via LUT[bid%148])
    const int bid = blockIdx.x;
    const int r   = (bid < 148) ? bid : 403 - bid;
    const int qt  = 63 - (r >> 2);
    const int b   = r & 3;
    const int q0  = qt * 64;

    const int tid = threadIdx.x;
    const int wid = tid >> 5, lane = tid & 31;
    const int g   = lane >> 2, t = lane & 3;
    const int wm  = wid * 16;

    const uint32_t smb  = (uint32_t)__cvta_generic_to_shared((void*)smattn);
    const uint32_t smKs = smb;
    const uint32_t smVs = smb + 2 * KBUF * 4;

    const int nkt = 2 * qt + 2;

    // prologue: prefetch K/V tile 0 into buffer 0
    {
        const uint32_t* kp = g_k + ((size_t)b * TT) * HH;
        const uint32_t* vp = g_v + ((size_t)b * TT) * HH;
#pragma unroll
        for (int u = 0; u < 8; u++) {
            int v = tid + u * 128;
            int rr = v >> 5, c4 = (v & 31) << 2;
            cp16(smKs + (uint32_t)(rr * SK + c4) * 4, kp + (size_t)rr * HH + c4);
            cp16(smVs + (uint32_t)(rr * SV + c4) * 4, vp + (size_t)rr * HH + c4);
        }
        asm volatile("cp.async.commit_group;");
    }

    // Q fragments -> registers from perm16 layout:
    // frag(ks) words (k=t, k=t+4) live at cols 16*(ks>>1) + 4t + 2*(ks&1) + {0,1}
    // NOTE: perm16 here packs fragment word pairs adjacently:
    //   logical col 8*ks+t (k=t) and 8*ks+t+4 (k=t+4), ks'=ks>>1:
    //   perm16 maps them to 16*ks' + 4t + 2*(ks&1) and +1.
    uint4 aq[16];
    {
        const uint32_t* qrow = g_q + ((size_t)b * TT + q0 + wm) * HH;
#pragma unroll
        for (int ks = 0; ks < 16; ks++) {
            int c = (ks >> 1) * 16 + 4 * t + 2 * (ks & 1);
            uint2 lo = *(const uint2*)&qrow[(size_t)g * HH + c];
            uint2 hi = *(const uint2*)&qrow[(size_t)(g + 8) * HH + c];
            aq[ks].x = lo.x;   // row g,   k=t
            aq[ks].y = hi.x;   // row g+8, k=t
            aq[ks].z = lo.y;   // row g,   k=t+4
            aq[ks].w = hi.y;   // row g+8, k=t+4
        }
    }

    float o[16][4];
#pragma unroll
    for (int jj = 0; jj < 16; jj++)
#pragma unroll
        for (int q = 0; q < 4; q++) o[jj][q] = 0.f;
    float m0 = -1e30f, m1 = -1e30f, l0 = 0.f, l1 = 0.f;

    for (int kt = 0; kt < nkt; kt++) {
        asm volatile("cp.async.wait_group 0;");
        __syncthreads();   // tile kt visible; buffer kt-1 free

        if (kt + 1 < nkt) {
            const int k0n = (kt + 1) * 32;
            const uint32_t* kp = g_k + ((size_t)b * TT + k0n) * HH;
            const uint32_t* vp = g_v + ((size_t)b * TT + k0n) * HH;
            const uint32_t kd = smKs + (uint32_t)(((kt + 1) & 1) * KBUF) * 4;
            const uint32_t vd = smVs + (uint32_t)(((kt + 1) & 1) * VBUF) * 4;
#pragma unroll
            for (int u = 0; u < 8; u++) {
                int v = tid + u * 128;
                int rr = v >> 5, c4 = (v & 31) << 2;
                cp16(kd + (uint32_t)(rr * SK + c4) * 4, kp + (size_t)rr * HH + c4);
                cp16(vd + (uint32_t)(rr * SV + c4) * 4, vp + (size_t)rr * HH + c4);
            }
            asm volatile("cp.async.commit_group;");
        }

        const uint32_t* Kc = Ks + (kt & 1) * KBUF;
        const uint32_t* Vc = Vs + (kt & 1) * VBUF;
        const int k0 = kt * 32;

        // ---- S = Q @ K^T (K fragments via LDS.64, conflict-free) ----
        float s[4][4];
#pragma unroll
        for (int j = 0; j < 4; j++)
#pragma unroll
            for (int q = 0; q < 4; q++) s[j][q] = 0.f;

#pragma unroll
        for (int ks = 0; ks < 16; ks++) {
            const uint4 a = aq[ks];
            const int c = (ks >> 1) * 16 + 4 * t + 2 * (ks & 1);
#pragma unroll
            for (int j = 0; j < 4; j++) {
                uint2 bb = *(const uint2*)&Kc[(j * 8 + g) * SK + c];
                mma8(s[j], a.x, a.y, a.z, a.w, bb.x, bb.y);
            }
        }

        // causal mask (only near the diagonal)
        if (k0 + 31 > q0 + wm) {
            int rlo = q0 + wm + g, rhi = rlo + 8;
#pragma unroll
            for (int j = 0; j < 4; j++) {
                int c = k0 + j * 8 + 2 * t;
                if (c     > rlo) s[j][0] = -1e30f;
                if (c + 1 > rlo) s[j][1] = -1e30f;
                if (c     > rhi) s[j][2] = -1e30f;
                if (c + 1 > rhi) s[j][3] = -1e30f;
            }
        }

        // ---- online softmax (base-2 domain) ----
        float mx0 = -1e30f, mx1 = -1e30f;
#pragma unroll
        for (int j = 0; j < 4; j++) {
            mx0 = fmaxf(mx0, fmaxf(s[j][0], s[j][1]));
            mx1 = fmaxf(mx1, fmaxf(s[j][2], s[j][3]));
        }
        mx0 = fmaxf(mx0, __shfl_xor_sync(0xffffffffu, mx0, 1));
        mx0 = fmaxf(mx0, __shfl_xor_sync(0xffffffffu, mx0, 2));
        mx1 = fmaxf(mx1, __shfl_xor_sync(0xffffffffu, mx1, 1));
        mx1 = fmaxf(mx1, __shfl_xor_sync(0xffffffffu, mx1, 2));

        float mn0 = fmaxf(m0, mx0), mn1 = fmaxf(m1, mx1);
        float al0 = exp2f(m0 - mn0), al1 = exp2f(m1 - mn1);
        float rs0 = 0.f, rs1 = 0.f;
#pragma unroll
        for (int j = 0; j < 4; j++) {
            s[j][0] = exp2f(s[j][0] - mn0); s[j][1] = exp2f(s[j][1] - mn0);
            s[j][2] = exp2f(s[j][2] - mn1); s[j][3] = exp2f(s[j][3] - mn1);
            rs0 += s[j][0] + s[j][1];
            rs1 += s[j][2] + s[j][3];
        }
        rs0 += __shfl_xor_sync(0xffffffffu, rs0, 1);
        rs0 += __shfl_xor_sync(0xffffffffu, rs0, 2);
        rs1 += __shfl_xor_sync(0xffffffffu, rs1, 1);
        rs1 += __shfl_xor_sync(0xffffffffu, rs1, 2);
        l0 = l0 * al0 + rs0;  l1 = l1 * al1 + rs1;
        m0 = mn0;  m1 = mn1;

#pragma unroll
        for (int jj = 0; jj < 16; jj++) {
            o[jj][0] *= al0; o[jj][1] *= al0;
            o[jj][2] *= al1; o[jj][3] *= al1;
        }

        // P -> smem (tf32); only this warp's rows, so syncwarp suffices
#pragma unroll
        for (int j = 0; j < 4; j++) {
            int c = j * 8 + 2 * t;
            Ps[(wm + g) * SP + c]         = f2tf(s[j][0]);
            Ps[(wm + g) * SP + c + 1]     = f2tf(s[j][1]);
            Ps[(wm + g + 8) * SP + c]     = f2tf(s[j][2]);
            Ps[(wm + g + 8) * SP + c + 1] = f2tf(s[j][3]);
        }
        __syncwarp();

        // ---- O += P @ V (V fragments via LDS.64 pairs, conflict-free) ----
#pragma unroll
        for (int kk = 0; kk < 32; kk += 8) {
            uint32_t a0 = Ps[(wm + g) * SP + kk + t];
            uint32_t a1 = Ps[(wm + g + 8) * SP + kk + t];
            uint32_t a2 = Ps[(wm + g) * SP + kk + t + 4];
            uint32_t a3 = Ps[(wm + g + 8) * SP + kk + t + 4];
#pragma unroll
            for (int p = 0; p < 8; p++) {
                uint2 b0p = *(const uint2*)&Vc[(kk + t) * SV + p * 16 + 2 * g];
                uint2 b1p = *(const uint2*)&Vc[(kk + t + 4) * SV + p * 16 + 2 * g];
                mma8(o[2 * p],     a0, a1, a2, a3, b0p.x, b1p.x);
                mma8(o[2 * p + 1], a0, a1, a2, a3, b0p.y, b1p.y);
            }
        }
    }

    // ---- epilogue ----
    float inv0 = 1.f / l0, inv1 = 1.f / l1;
    int rlo = q0 + wm + g, rhi = rlo + 8;
    float* olo = out + ((size_t)b * TT + rlo) * HH;
    float* ohi = out + ((size_t)b * TT + rhi) * HH;
#pragma unroll
    for (int jj = 0; jj < 16; jj++) {
        int c = jj * 8 + 2 * t;
        float2 v0 = make_float2(o[jj][0] * inv0, o[jj][1] * inv0);
        float2 v1 = make_float2(o[jj][2] * inv1, o[jj][3] * inv1);
        *(float2*)&olo[c] = v0;
        *(float2*)&ohi[c] = v1;
    }
}

// ---------------------------------------------------------------------------
extern "C" void kernel_launch(void* const* d_in, const int* in_sizes, int n_in,
                              void* d_out, int out_size)
{
    const float* x  = (const float*)d_in[0];
    const float* Wk = (const float*)d_in[1];
    const float* Wq = (const float*)d_in[2];
    const float* Wv = (const float*)d_in[3];
    float* out = (float*)d_out;

    (void)in_sizes; (void)n_in; (void)out_size;

    const int proj_smem = (2 * PXS + 2 * PWS) * 4;   // 71680 (>= 128*132*4 staging)
    cudaFuncSetAttribute(proj_kernel,
                         cudaFuncAttributeMaxDynamicSharedMemorySize,
                         proj_smem);
    dim3 pgrid((BB * TT) / 128, 3);
    proj_kernel<<<pgrid, 256, proj_smem>>>(x, Wk, Wq, Wv);

    const int attn_smem = (2 * KBUF + 2 * VBUF + 64 * SP) * 4;  // 78848
    cudaFuncSetAttribute(attn_kernel,
                         cudaFuncAttributeMaxDynamicSharedMemorySize,
                         attn_smem);
    attn_kernel<<<BB * NQT, 128, attn_smem>>>(out);
}

// round 11
// speedup vs baseline: 1.1118x; 1.1118x over previous
#include <cuda_runtime.h>
#include <stdint.h>
#include <math.h>

#define BB 4
#define TT 4096
#define CC 1024
#define HH 128
#define NQT 64

// projection scratch, tf32 bit patterns, h-dim PERMUTED per tensor:
//  g_q/g_k: permQK: c -> (c&~7)|((c&3)<<1)|((c>>2)&1)  (frag words k=t,t+4 adjacent)
//  g_v:     permV:  c -> (c&~15)|((c&7)<<1)|((c>>3)&1) (n-block pairs adjacent)
// q pre-scaled by H^-0.5*log2(e)
__device__ uint32_t g_q[BB * TT * HH];
__device__ uint32_t g_k[BB * TT * HH];
__device__ uint32_t g_v[BB * TT * HH];

__device__ __forceinline__ uint32_t f2tf(float x) {
    uint32_t r;
    asm("cvt.rna.tf32.f32 %0, %1;" : "=r"(r) : "f"(x));
    return r;
}

__device__ __forceinline__ int permQK(int c) {
    return (c & ~7) | ((c & 3) << 1) | ((c >> 2) & 1);
}
__device__ __forceinline__ int permV(int c) {
    return (c & ~15) | ((c & 7) << 1) | ((c >> 3) & 1);
}

__device__ __forceinline__ void mma8(float c[4],
                                     uint32_t a0, uint32_t a1, uint32_t a2, uint32_t a3,
                                     uint32_t b0, uint32_t b1)
{
    asm volatile(
        "mma.sync.aligned.m16n8k8.row.col.f32.tf32.tf32.f32 "
        "{%0,%1,%2,%3},{%4,%5,%6,%7},{%8,%9},{%0,%1,%2,%3};"
        : "+f"(c[0]), "+f"(c[1]), "+f"(c[2]), "+f"(c[3])
        : "r"(a0), "r"(a1), "r"(a2), "r"(a3), "r"(b0), "r"(b1));
}

__device__ __forceinline__ void cp16(uint32_t dst, const void* src) {
    asm volatile("cp.async.cg.shared.global [%0], [%1], 16;"
                 :: "r"(dst), "l"(src));
}

// ---------------------------------------------------------------------------
// Projection: y = x @ W via tf32 mma. M=16384, K=1024, N=128.
// cp.async double-buffered mainloop; epilogue stages permuted values in smem
// then writes GMEM fully coalesced (uint4). (R9 proj, permQK layout.)
// ---------------------------------------------------------------------------
#define PXS 4608   // 128*36 floats per X stage
#define PWS 4352   // 32*136 floats per W stage
#define PES 132    // epilogue staging row stride

__global__ void __launch_bounds__(256, 2) proj_kernel(
    const float* __restrict__ x,
    const float* __restrict__ Wk,
    const float* __restrict__ Wq,
    const float* __restrict__ Wv)
{
    extern __shared__ float psm[];

    const int z = blockIdx.y;
    const float* W = (z == 0) ? Wq : (z == 1) ? Wk : Wv;
    uint32_t* y    = (z == 0) ? g_q : (z == 1) ? g_k : g_v;
    const float oscale = (z == 0) ? (0.08838834764831845f * 1.4426950408889634f) : 1.0f;
    const bool isV = (z == 2);

    const int row0 = blockIdx.x * 128;
    const int tid  = threadIdx.x;
    const int wid  = tid >> 5, lane = tid & 31;
    const int wm   = (wid >> 1) * 32, wn = (wid & 1) * 64;
    const int g    = lane >> 2, t = lane & 3;

    uint32_t smb = (uint32_t)__cvta_generic_to_shared((void*)psm);

    float acc[2][8][4];
#pragma unroll
    for (int i = 0; i < 2; i++)
#pragma unroll
        for (int j = 0; j < 8; j++)
#pragma unroll
            for (int q = 0; q < 4; q++) acc[i][j][q] = 0.f;

    {
        const uint32_t xd = smb;
        const uint32_t wd = smb + 2 * PXS * 4;
#pragma unroll
        for (int u = 0; u < 4; u++) {
            int v = tid + u * 256;
            int rx = v >> 3, cx = (v & 7) << 2;
            cp16(xd + (uint32_t)(rx * 36 + cx) * 4,
                 &x[(size_t)(row0 + rx) * CC + cx]);
            int rw = v >> 5, cw = (v & 31) << 2;
            cp16(wd + (uint32_t)(rw * 136 + cw) * 4,
                 &W[(size_t)rw * HH + cw]);
        }
        asm volatile("cp.async.commit_group;");
    }

    for (int k0 = 0; k0 < CC; k0 += 32) {
        asm volatile("cp.async.wait_group 0;");
        __syncthreads();

        const int st = (k0 >> 5) & 1;
        if (k0 + 32 < CC) {
            const int sn = st ^ 1;
            const uint32_t xd = smb + (uint32_t)(sn * PXS) * 4;
            const uint32_t wd = smb + (uint32_t)(2 * PXS + sn * PWS) * 4;
#pragma unroll
            for (int u = 0; u < 4; u++) {
                int v = tid + u * 256;
                int rx = v >> 3, cx = (v & 7) << 2;
                cp16(xd + (uint32_t)(rx * 36 + cx) * 4,
                     &x[(size_t)(row0 + rx) * CC + k0 + 32 + cx]);
                int rw = v >> 5, cw = (v & 31) << 2;
                cp16(wd + (uint32_t)(rw * 136 + cw) * 4,
                     &W[(size_t)(k0 + 32 + rw) * HH + cw]);
            }
            asm volatile("cp.async.commit_group;");
        }

        const float* Xs = psm + st * PXS;
        const float* Ws = psm + 2 * PXS + st * PWS;

#pragma unroll
        for (int ks = 0; ks < 32; ks += 8) {
            uint32_t a[2][4], bfr[8][2];
#pragma unroll
            for (int i = 0; i < 2; i++) {
                int r = wm + i * 16;
                a[i][0] = f2tf(Xs[(r + g) * 36 + ks + t]);
                a[i][1] = f2tf(Xs[(r + g + 8) * 36 + ks + t]);
                a[i][2] = f2tf(Xs[(r + g) * 36 + ks + t + 4]);
                a[i][3] = f2tf(Xs[(r + g + 8) * 36 + ks + t + 4]);
            }
#pragma unroll
            for (int j = 0; j < 8; j++) {
                int c = wn + j * 8 + g;
                bfr[j][0] = f2tf(Ws[(ks + t) * 136 + c]);
                bfr[j][1] = f2tf(Ws[(ks + t + 4) * 136 + c]);
            }
#pragma unroll
            for (int i = 0; i < 2; i++)
#pragma unroll
                for (int j = 0; j < 8; j++)
                    mma8(acc[i][j], a[i][0], a[i][1], a[i][2], a[i][3],
                         bfr[j][0], bfr[j][1]);
        }
    }

    // ---- epilogue: permuted scatter into smem, then coalesced STG.128 ----
    __syncthreads();   // all warps done reading pipeline stages
    uint32_t* Ss = (uint32_t*)psm;   // [128][PES]
#pragma unroll
    for (int i = 0; i < 2; i++) {
        int rlo = wm + i * 16 + g;
        int rhi = rlo + 8;
#pragma unroll
        for (int j = 0; j < 8; j++) {
            int c0 = wn + j * 8 + 2 * t;
            int c1 = c0 + 1;
            int p0 = isV ? permV(c0) : permQK(c0);
            int p1 = isV ? permV(c1) : permQK(c1);
            Ss[rlo * PES + p0] = f2tf(acc[i][j][0] * oscale);
            Ss[rlo * PES + p1] = f2tf(acc[i][j][1] * oscale);
            Ss[rhi * PES + p0] = f2tf(acc[i][j][2] * oscale);
            Ss[rhi * PES + p1] = f2tf(acc[i][j][3] * oscale);
        }
    }
    __syncthreads();
#pragma unroll
    for (int u = 0; u < 16; u++) {
        int v = tid + u * 256;
        int rr = v >> 5, c4 = (v & 31) << 2;
        *(uint4*)&y[(size_t)(row0 + rr) * HH + c4] =
            *(const uint4*)&Ss[rr * PES + c4];
    }
}

// ---------------------------------------------------------------------------
// Flash attention (causal), tf32 mma, BM=64, BN=32, 128 threads (4 warps).
// BYTE-EXACT R6 structure (best measured 212.2us): K/V fragments via LDS.64
// in permQK/permV layouts, rescale every iter, single barrier per k-tile.
// ---------------------------------------------------------------------------
#define SK 136
#define SV 136
#define SP 36
#define KBUF (32 * SK)
#define VBUF (32 * SV)

__global__ void __launch_bounds__(128, 2) attn_kernel(float* __restrict__ out)
{
    extern __shared__ uint32_t smattn[];
    uint32_t* Ks = smattn;              // 2 x [32][136]
    uint32_t* Vs = Ks + 2 * KBUF;       // 2 x [32][136]
    uint32_t* Ps = Vs + 2 * VBUF;       // [64][36]

    // balanced schedule: pair bid s with s+148 (same SM via LUT[bid%148])
    const int bid = blockIdx.x;
    const int r   = (bid < 148) ? bid : 403 - bid;
    const int qt  = 63 - (r >> 2);
    const int b   = r & 3;
    const int q0  = qt * 64;

    const int tid = threadIdx.x;
    const int wid = tid >> 5, lane = tid & 31;
    const int g   = lane >> 2, t = lane & 3;
    const int wm  = wid * 16;

    const uint32_t smb  = (uint32_t)__cvta_generic_to_shared((void*)smattn);
    const uint32_t smKs = smb;
    const uint32_t smVs = smb + 2 * KBUF * 4;

    const int nkt = 2 * qt + 2;

    // prologue: prefetch K/V tile 0 into buffer 0
    {
        const uint32_t* kp = g_k + ((size_t)b * TT) * HH;
        const uint32_t* vp = g_v + ((size_t)b * TT) * HH;
#pragma unroll
        for (int u = 0; u < 8; u++) {
            int v = tid + u * 128;
            int rr = v >> 5, c4 = (v & 31) << 2;
            cp16(smKs + (uint32_t)(rr * SK + c4) * 4, kp + (size_t)rr * HH + c4);
            cp16(smVs + (uint32_t)(rr * SV + c4) * 4, vp + (size_t)rr * HH + c4);
        }
        asm volatile("cp.async.commit_group;");
    }

    // Q fragments -> registers (permQK layout: k=t at col 8ks+2t, k=t+4 at +1)
    uint4 aq[16];
    {
        const uint32_t* qrow = g_q + ((size_t)b * TT + q0 + wm) * HH;
#pragma unroll
        for (int ks = 0; ks < 16; ks++) {
            uint2 lo = *(const uint2*)&qrow[(size_t)g * HH + ks * 8 + 2 * t];
            uint2 hi = *(const uint2*)&qrow[(size_t)(g + 8) * HH + ks * 8 + 2 * t];
            aq[ks].x = lo.x;   // row g,   k=t
            aq[ks].y = hi.x;   // row g+8, k=t
            aq[ks].z = lo.y;   // row g,   k=t+4
            aq[ks].w = hi.y;   // row g+8, k=t+4
        }
    }

    float o[16][4];
#pragma unroll
    for (int jj = 0; jj < 16; jj++)
#pragma unroll
        for (int q = 0; q < 4; q++) o[jj][q] = 0.f;
    float m0 = -1e30f, m1 = -1e30f, l0 = 0.f, l1 = 0.f;

    for (int kt = 0; kt < nkt; kt++) {
        asm volatile("cp.async.wait_group 0;");
        __syncthreads();   // tile kt visible; buffer kt-1 free

        if (kt + 1 < nkt) {
            const int k0n = (kt + 1) * 32;
            const uint32_t* kp = g_k + ((size_t)b * TT + k0n) * HH;
            const uint32_t* vp = g_v + ((size_t)b * TT + k0n) * HH;
            const uint32_t kd = smKs + (uint32_t)(((kt + 1) & 1) * KBUF) * 4;
            const uint32_t vd = smVs + (uint32_t)(((kt + 1) & 1) * VBUF) * 4;
#pragma unroll
            for (int u = 0; u < 8; u++) {
                int v = tid + u * 128;
                int rr = v >> 5, c4 = (v & 31) << 2;
                cp16(kd + (uint32_t)(rr * SK + c4) * 4, kp + (size_t)rr * HH + c4);
                cp16(vd + (uint32_t)(rr * SV + c4) * 4, vp + (size_t)rr * HH + c4);
            }
            asm volatile("cp.async.commit_group;");
        }

        const uint32_t* Kc = Ks + (kt & 1) * KBUF;
        const uint32_t* Vc = Vs + (kt & 1) * VBUF;
        const int k0 = kt * 32;

        // ---- S = Q @ K^T (K fragments via LDS.64, conflict-free) ----
        float s[4][4];
#pragma unroll
        for (int j = 0; j < 4; j++)
#pragma unroll
            for (int q = 0; q < 4; q++) s[j][q] = 0.f;

#pragma unroll
        for (int ks = 0; ks < 16; ks++) {
            const uint4 a = aq[ks];
#pragma unroll
            for (int j = 0; j < 4; j++) {
                uint2 bb = *(const uint2*)&Kc[(j * 8 + g) * SK + ks * 8 + 2 * t];
                mma8(s[j], a.x, a.y, a.z, a.w, bb.x, bb.y);
            }
        }

        // causal mask (only near the diagonal)
        if (k0 + 31 > q0 + wm) {
            int rlo = q0 + wm + g, rhi = rlo + 8;
#pragma unroll
            for (int j = 0; j < 4; j++) {
                int c = k0 + j * 8 + 2 * t;
                if (c     > rlo) s[j][0] = -1e30f;
                if (c + 1 > rlo) s[j][1] = -1e30f;
                if (c     > rhi) s[j][2] = -1e30f;
                if (c + 1 > rhi) s[j][3] = -1e30f;
            }
        }

        // ---- online softmax (base-2 domain) ----
        float mx0 = -1e30f, mx1 = -1e30f;
#pragma unroll
        for (int j = 0; j < 4; j++) {
            mx0 = fmaxf(mx0, fmaxf(s[j][0], s[j][1]));
            mx1 = fmaxf(mx1, fmaxf(s[j][2], s[j][3]));
        }
        mx0 = fmaxf(mx0, __shfl_xor_sync(0xffffffffu, mx0, 1));
        mx0 = fmaxf(mx0, __shfl_xor_sync(0xffffffffu, mx0, 2));
        mx1 = fmaxf(mx1, __shfl_xor_sync(0xffffffffu, mx1, 1));
        mx1 = fmaxf(mx1, __shfl_xor_sync(0xffffffffu, mx1, 2));

        float mn0 = fmaxf(m0, mx0), mn1 = fmaxf(m1, mx1);
        float al0 = exp2f(m0 - mn0), al1 = exp2f(m1 - mn1);
        float rs0 = 0.f, rs1 = 0.f;
#pragma unroll
        for (int j = 0; j < 4; j++) {
            s[j][0] = exp2f(s[j][0] - mn0); s[j][1] = exp2f(s[j][1] - mn0);
            s[j][2] = exp2f(s[j][2] - mn1); s[j][3] = exp2f(s[j][3] - mn1);
            rs0 += s[j][0] + s[j][1];
            rs1 += s[j][2] + s[j][3];
        }
        rs0 += __shfl_xor_sync(0xffffffffu, rs0, 1);
        rs0 += __shfl_xor_sync(0xffffffffu, rs0, 2);
        rs1 += __shfl_xor_sync(0xffffffffu, rs1, 1);
        rs1 += __shfl_xor_sync(0xffffffffu, rs1, 2);
        l0 = l0 * al0 + rs0;  l1 = l1 * al1 + rs1;
        m0 = mn0;  m1 = mn1;

#pragma unroll
        for (int jj = 0; jj < 16; jj++) {
            o[jj][0] *= al0; o[jj][1] *= al0;
            o[jj][2] *= al1; o[jj][3] *= al1;
        }

        // P -> smem (tf32); only this warp's rows, so syncwarp suffices
#pragma unroll
        for (int j = 0; j < 4; j++) {
            int c = j * 8 + 2 * t;
            Ps[(wm + g) * SP + c]         = f2tf(s[j][0]);
            Ps[(wm + g) * SP + c + 1]     = f2tf(s[j][1]);
            Ps[(wm + g + 8) * SP + c]     = f2tf(s[j][2]);
            Ps[(wm + g + 8) * SP + c + 1] = f2tf(s[j][3]);
        }
        __syncwarp();

        // ---- O += P @ V (V fragments via LDS.64 pairs, conflict-free) ----
#pragma unroll
        for (int kk = 0; kk < 32; kk += 8) {
            uint32_t a0 = Ps[(wm + g) * SP + kk + t];
            uint32_t a1 = Ps[(wm + g + 8) * SP + kk + t];
            uint32_t a2 = Ps[(wm + g) * SP + kk + t + 4];
            uint32_t a3 = Ps[(wm + g + 8) * SP + kk + t + 4];
#pragma unroll
            for (int p = 0; p < 8; p++) {
                uint2 b0p = *(const uint2*)&Vc[(kk + t) * SV + p * 16 + 2 * g];
                uint2 b1p = *(const uint2*)&Vc[(kk + t + 4) * SV + p * 16 + 2 * g];
                mma8(o[2 * p],     a0, a1, a2, a3, b0p.x, b1p.x);
                mma8(o[2 * p + 1], a0, a1, a2, a3, b0p.y, b1p.y);
            }
        }
    }

    // ---- epilogue ----
    float inv0 = 1.f / l0, inv1 = 1.f / l1;
    int rlo = q0 + wm + g, rhi = rlo + 8;
    float* olo = out + ((size_t)b * TT + rlo) * HH;
    float* ohi = out + ((size_t)b * TT + rhi) * HH;
#pragma unroll
    for (int jj = 0; jj < 16; jj++) {
        int c = jj * 8 + 2 * t;
        float2 v0 = make_float2(o[jj][0] * inv0, o[jj][1] * inv0);
        float2 v1 = make_float2(o[jj][2] * inv1, o[jj][3] * inv1);
        *(float2*)&olo[c] = v0;
        *(float2*)&ohi[c] = v1;
    }
}

// ---------------------------------------------------------------------------
extern "C" void kernel_launch(void* const* d_in, const int* in_sizes, int n_in,
                              void* d_out, int out_size)
{
    const float* x  = (const float*)d_in[0];
    const float* Wk = (const float*)d_in[1];
    const float* Wq = (const float*)d_in[2];
    const float* Wv = (const float*)d_in[3];
    float* out = (float*)d_out;

    (void)in_sizes; (void)n_in; (void)out_size;

    const int proj_smem = (2 * PXS + 2 * PWS) * 4;   // 71680 (>= 128*132*4 staging)
    cudaFuncSetAttribute(proj_kernel,
                         cudaFuncAttributeMaxDynamicSharedMemorySize,
                         proj_smem);
    dim3 pgrid((BB * TT) / 128, 3);
    proj_kernel<<<pgrid, 256, proj_smem>>>(x, Wk, Wq, Wv);

    const int attn_smem = (2 * KBUF + 2 * VBUF + 64 * SP) * 4;  // 78848
    cudaFuncSetAttribute(attn_kernel,
                         cudaFuncAttributeMaxDynamicSharedMemorySize,
                         attn_smem);
    attn_kernel<<<BB * NQT, 128, attn_smem>>>(out);
}

// round 12
// speedup vs baseline: 1.1158x; 1.0036x over previous
#include <cuda_runtime.h>
#include <stdint.h>
#include <math.h>

#define BB 4
#define TT 4096
#define CC 1024
#define HH 128
#define NQT 64

// projection scratch, tf32 bit patterns, h-dim PERMUTED per tensor:
//  g_q/g_k: permQK: c -> (c&~7)|((c&3)<<1)|((c>>2)&1)  (frag words k=t,t+4 adjacent)
//  g_v:     permV:  c -> (c&~15)|((c&7)<<1)|((c>>3)&1) (n-block pairs adjacent)
// q pre-scaled by H^-0.5*log2(e)
__device__ uint32_t g_q[BB * TT * HH];
__device__ uint32_t g_k[BB * TT * HH];
__device__ uint32_t g_v[BB * TT * HH];

__device__ __forceinline__ uint32_t f2tf(float x) {
    uint32_t r;
    asm("cvt.rna.tf32.f32 %0, %1;" : "=r"(r) : "f"(x));
    return r;
}

__device__ __forceinline__ int permQK(int c) {
    return (c & ~7) | ((c & 3) << 1) | ((c >> 2) & 1);
}
__device__ __forceinline__ int permV(int c) {
    return (c & ~15) | ((c & 7) << 1) | ((c >> 3) & 1);
}

__device__ __forceinline__ void mma8(float c[4],
                                     uint32_t a0, uint32_t a1, uint32_t a2, uint32_t a3,
                                     uint32_t b0, uint32_t b1)
{
    asm volatile(
        "mma.sync.aligned.m16n8k8.row.col.f32.tf32.tf32.f32 "
        "{%0,%1,%2,%3},{%4,%5,%6,%7},{%8,%9},{%0,%1,%2,%3};"
        : "+f"(c[0]), "+f"(c[1]), "+f"(c[2]), "+f"(c[3])
        : "r"(a0), "r"(a1), "r"(a2), "r"(a3), "r"(b0), "r"(b1));
}

__device__ __forceinline__ void cp16(uint32_t dst, const void* src) {
    asm volatile("cp.async.cg.shared.global [%0], [%1], 16;"
                 :: "r"(dst), "l"(src));
}

// ---------------------------------------------------------------------------
// Projection: y = x @ W via tf32 mma. M=16384, K=1024, N=128.
// cp.async double-buffered mainloop; epilogue stages permuted values in smem
// then writes GMEM fully coalesced (uint4). (Validated R10 proj, ~36.6us.)
// ---------------------------------------------------------------------------
#define PXS 4608   // 128*36 floats per X stage
#define PWS 4352   // 32*136 floats per W stage
#define PES 132    // epilogue staging row stride

__global__ void __launch_bounds__(256, 2) proj_kernel(
    const float* __restrict__ x,
    const float* __restrict__ Wk,
    const float* __restrict__ Wq,
    const float* __restrict__ Wv)
{
    extern __shared__ float psm[];

    const int z = blockIdx.y;
    const float* W = (z == 0) ? Wq : (z == 1) ? Wk : Wv;
    uint32_t* y    = (z == 0) ? g_q : (z == 1) ? g_k : g_v;
    const float oscale = (z == 0) ? (0.08838834764831845f * 1.4426950408889634f) : 1.0f;
    const bool isV = (z == 2);

    const int row0 = blockIdx.x * 128;
    const int tid  = threadIdx.x;
    const int wid  = tid >> 5, lane = tid & 31;
    const int wm   = (wid >> 1) * 32, wn = (wid & 1) * 64;
    const int g    = lane >> 2, t = lane & 3;

    uint32_t smb = (uint32_t)__cvta_generic_to_shared((void*)psm);

    float acc[2][8][4];
#pragma unroll
    for (int i = 0; i < 2; i++)
#pragma unroll
        for (int j = 0; j < 8; j++)
#pragma unroll
            for (int q = 0; q < 4; q++) acc[i][j][q] = 0.f;

    {
        const uint32_t xd = smb;
        const uint32_t wd = smb + 2 * PXS * 4;
#pragma unroll
        for (int u = 0; u < 4; u++) {
            int v = tid + u * 256;
            int rx = v >> 3, cx = (v & 7) << 2;
            cp16(xd + (uint32_t)(rx * 36 + cx) * 4,
                 &x[(size_t)(row0 + rx) * CC + cx]);
            int rw = v >> 5, cw = (v & 31) << 2;
            cp16(wd + (uint32_t)(rw * 136 + cw) * 4,
                 &W[(size_t)rw * HH + cw]);
        }
        asm volatile("cp.async.commit_group;");
    }

    for (int k0 = 0; k0 < CC; k0 += 32) {
        asm volatile("cp.async.wait_group 0;");
        __syncthreads();

        const int st = (k0 >> 5) & 1;
        if (k0 + 32 < CC) {
            const int sn = st ^ 1;
            const uint32_t xd = smb + (uint32_t)(sn * PXS) * 4;
            const uint32_t wd = smb + (uint32_t)(2 * PXS + sn * PWS) * 4;
#pragma unroll
            for (int u = 0; u < 4; u++) {
                int v = tid + u * 256;
                int rx = v >> 3, cx = (v & 7) << 2;
                cp16(xd + (uint32_t)(rx * 36 + cx) * 4,
                     &x[(size_t)(row0 + rx) * CC + k0 + 32 + cx]);
                int rw = v >> 5, cw = (v & 31) << 2;
                cp16(wd + (uint32_t)(rw * 136 + cw) * 4,
                     &W[(size_t)(k0 + 32 + rw) * HH + cw]);
            }
            asm volatile("cp.async.commit_group;");
        }

        const float* Xs = psm + st * PXS;
        const float* Ws = psm + 2 * PXS + st * PWS;

#pragma unroll
        for (int ks = 0; ks < 32; ks += 8) {
            uint32_t a[2][4], bfr[8][2];
#pragma unroll
            for (int i = 0; i < 2; i++) {
                int r = wm + i * 16;
                a[i][0] = f2tf(Xs[(r + g) * 36 + ks + t]);
                a[i][1] = f2tf(Xs[(r + g + 8) * 36 + ks + t]);
                a[i][2] = f2tf(Xs[(r + g) * 36 + ks + t + 4]);
                a[i][3] = f2tf(Xs[(r + g + 8) * 36 + ks + t + 4]);
            }
#pragma unroll
            for (int j = 0; j < 8; j++) {
                int c = wn + j * 8 + g;
                bfr[j][0] = f2tf(Ws[(ks + t) * 136 + c]);
                bfr[j][1] = f2tf(Ws[(ks + t + 4) * 136 + c]);
            }
#pragma unroll
            for (int i = 0; i < 2; i++)
#pragma unroll
                for (int j = 0; j < 8; j++)
                    mma8(acc[i][j], a[i][0], a[i][1], a[i][2], a[i][3],
                         bfr[j][0], bfr[j][1]);
        }
    }

    // ---- epilogue: permuted scatter into smem, then coalesced STG.128 ----
    __syncthreads();   // all warps done reading pipeline stages
    uint32_t* Ss = (uint32_t*)psm;   // [128][PES]
#pragma unroll
    for (int i = 0; i < 2; i++) {
        int rlo = wm + i * 16 + g;
        int rhi = rlo + 8;
#pragma unroll
        for (int j = 0; j < 8; j++) {
            int c0 = wn + j * 8 + 2 * t;
            int c1 = c0 + 1;
            int p0 = isV ? permV(c0) : permQK(c0);
            int p1 = isV ? permV(c1) : permQK(c1);
            Ss[rlo * PES + p0] = f2tf(acc[i][j][0] * oscale);
            Ss[rlo * PES + p1] = f2tf(acc[i][j][1] * oscale);
            Ss[rhi * PES + p0] = f2tf(acc[i][j][2] * oscale);
            Ss[rhi * PES + p1] = f2tf(acc[i][j][3] * oscale);
        }
    }
    __syncthreads();
#pragma unroll
    for (int u = 0; u < 16; u++) {
        int v = tid + u * 256;
        int rr = v >> 5, c4 = (v & 31) << 2;
        *(uint4*)&y[(size_t)(row0 + rr) * HH + c4] =
            *(const uint4*)&Ss[rr * PES + c4];
    }
}

// ---------------------------------------------------------------------------
// Flash attention (causal), tf32 mma, BM=64, BN=32, 128 threads (4 warps).
// R6 structure + (a) P-store hoisted before O-rescale, (b) alpha-skip rescale.
// Both changes are value-exact (skipping *1.0 is identity; reorder is pure).
// ---------------------------------------------------------------------------
#define SK 136
#define SV 136
#define SP 36
#define KBUF (32 * SK)
#define VBUF (32 * SV)

__global__ void __launch_bounds__(128, 2) attn_kernel(float* __restrict__ out)
{
    extern __shared__ uint32_t smattn[];
    uint32_t* Ks = smattn;              // 2 x [32][136]
    uint32_t* Vs = Ks + 2 * KBUF;       // 2 x [32][136]
    uint32_t* Ps = Vs + 2 * VBUF;       // [64][36]

    // balanced schedule: pair bid s with s+148 (same SM via LUT[bid%148])
    const int bid = blockIdx.x;
    const int r   = (bid < 148) ? bid : 403 - bid;
    const int qt  = 63 - (r >> 2);
    const int b   = r & 3;
    const int q0  = qt * 64;

    const int tid = threadIdx.x;
    const int wid = tid >> 5, lane = tid & 31;
    const int g   = lane >> 2, t = lane & 3;
    const int wm  = wid * 16;

    const uint32_t smb  = (uint32_t)__cvta_generic_to_shared((void*)smattn);
    const uint32_t smKs = smb;
    const uint32_t smVs = smb + 2 * KBUF * 4;

    const int nkt = 2 * qt + 2;

    // prologue: prefetch K/V tile 0 into buffer 0
    {
        const uint32_t* kp = g_k + ((size_t)b * TT) * HH;
        const uint32_t* vp = g_v + ((size_t)b * TT) * HH;
#pragma unroll
        for (int u = 0; u < 8; u++) {
            int v = tid + u * 128;
            int rr = v >> 5, c4 = (v & 31) << 2;
            cp16(smKs + (uint32_t)(rr * SK + c4) * 4, kp + (size_t)rr * HH + c4);
            cp16(smVs + (uint32_t)(rr * SV + c4) * 4, vp + (size_t)rr * HH + c4);
        }
        asm volatile("cp.async.commit_group;");
    }

    // Q fragments -> registers (permQK layout: k=t at col 8ks+2t, k=t+4 at +1)
    uint4 aq[16];
    {
        const uint32_t* qrow = g_q + ((size_t)b * TT + q0 + wm) * HH;
#pragma unroll
        for (int ks = 0; ks < 16; ks++) {
            uint2 lo = *(const uint2*)&qrow[(size_t)g * HH + ks * 8 + 2 * t];
            uint2 hi = *(const uint2*)&qrow[(size_t)(g + 8) * HH + ks * 8 + 2 * t];
            aq[ks].x = lo.x;   // row g,   k=t
            aq[ks].y = hi.x;   // row g+8, k=t
            aq[ks].z = lo.y;   // row g,   k=t+4
            aq[ks].w = hi.y;   // row g+8, k=t+4
        }
    }

    float o[16][4];
#pragma unroll
    for (int jj = 0; jj < 16; jj++)
#pragma unroll
        for (int q = 0; q < 4; q++) o[jj][q] = 0.f;
    float m0 = -1e30f, m1 = -1e30f, l0 = 0.f, l1 = 0.f;

    for (int kt = 0; kt < nkt; kt++) {
        asm volatile("cp.async.wait_group 0;");
        __syncthreads();   // tile kt visible; buffer kt-1 free

        if (kt + 1 < nkt) {
            const int k0n = (kt + 1) * 32;
            const uint32_t* kp = g_k + ((size_t)b * TT + k0n) * HH;
            const uint32_t* vp = g_v + ((size_t)b * TT + k0n) * HH;
            const uint32_t kd = smKs + (uint32_t)(((kt + 1) & 1) * KBUF) * 4;
            const uint32_t vd = smVs + (uint32_t)(((kt + 1) & 1) * VBUF) * 4;
#pragma unroll
            for (int u = 0; u < 8; u++) {
                int v = tid + u * 128;
                int rr = v >> 5, c4 = (v & 31) << 2;
                cp16(kd + (uint32_t)(rr * SK + c4) * 4, kp + (size_t)rr * HH + c4);
                cp16(vd + (uint32_t)(rr * SV + c4) * 4, vp + (size_t)rr * HH + c4);
            }
            asm volatile("cp.async.commit_group;");
        }

        const uint32_t* Kc = Ks + (kt & 1) * KBUF;
        const uint32_t* Vc = Vs + (kt & 1) * VBUF;
        const int k0 = kt * 32;

        // ---- S = Q @ K^T (K fragments via LDS.64, conflict-free) ----
        float s[4][4];
#pragma unroll
        for (int j = 0; j < 4; j++)
#pragma unroll
            for (int q = 0; q < 4; q++) s[j][q] = 0.f;

#pragma unroll
        for (int ks = 0; ks < 16; ks++) {
            const uint4 a = aq[ks];
#pragma unroll
            for (int j = 0; j < 4; j++) {
                uint2 bb = *(const uint2*)&Kc[(j * 8 + g) * SK + ks * 8 + 2 * t];
                mma8(s[j], a.x, a.y, a.z, a.w, bb.x, bb.y);
            }
        }

        // causal mask (only near the diagonal)
        if (k0 + 31 > q0 + wm) {
            int rlo = q0 + wm + g, rhi = rlo + 8;
#pragma unroll
            for (int j = 0; j < 4; j++) {
                int c = k0 + j * 8 + 2 * t;
                if (c     > rlo) s[j][0] = -1e30f;
                if (c + 1 > rlo) s[j][1] = -1e30f;
                if (c     > rhi) s[j][2] = -1e30f;
                if (c + 1 > rhi) s[j][3] = -1e30f;
            }
        }

        // ---- online softmax (base-2 domain) ----
        float mx0 = -1e30f, mx1 = -1e30f;
#pragma unroll
        for (int j = 0; j < 4; j++) {
            mx0 = fmaxf(mx0, fmaxf(s[j][0], s[j][1]));
            mx1 = fmaxf(mx1, fmaxf(s[j][2], s[j][3]));
        }
        mx0 = fmaxf(mx0, __shfl_xor_sync(0xffffffffu, mx0, 1));
        mx0 = fmaxf(mx0, __shfl_xor_sync(0xffffffffu, mx0, 2));
        mx1 = fmaxf(mx1, __shfl_xor_sync(0xffffffffu, mx1, 1));
        mx1 = fmaxf(mx1, __shfl_xor_sync(0xffffffffu, mx1, 2));

        float mn0 = fmaxf(m0, mx0), mn1 = fmaxf(m1, mx1);
        float al0 = exp2f(m0 - mn0), al1 = exp2f(m1 - mn1);
        float rs0 = 0.f, rs1 = 0.f;
#pragma unroll
        for (int j = 0; j < 4; j++) {
            s[j][0] = exp2f(s[j][0] - mn0); s[j][1] = exp2f(s[j][1] - mn0);
            s[j][2] = exp2f(s[j][2] - mn1); s[j][3] = exp2f(s[j][3] - mn1);
            rs0 += s[j][0] + s[j][1];
            rs1 += s[j][2] + s[j][3];
        }

        // ---- P -> smem early (STS latency overlaps the work below) ----
#pragma unroll
        for (int j = 0; j < 4; j++) {
            int c = j * 8 + 2 * t;
            Ps[(wm + g) * SP + c]         = f2tf(s[j][0]);
            Ps[(wm + g) * SP + c + 1]     = f2tf(s[j][1]);
            Ps[(wm + g + 8) * SP + c]     = f2tf(s[j][2]);
            Ps[(wm + g + 8) * SP + c + 1] = f2tf(s[j][3]);
        }

        rs0 += __shfl_xor_sync(0xffffffffu, rs0, 1);
        rs0 += __shfl_xor_sync(0xffffffffu, rs0, 2);
        rs1 += __shfl_xor_sync(0xffffffffu, rs1, 1);
        rs1 += __shfl_xor_sync(0xffffffffu, rs1, 2);
        l0 = l0 * al0 + rs0;  l1 = l1 * al1 + rs1;
        m0 = mn0;  m1 = mn1;

        // ---- alpha-skip O rescale (exact: skipping *1.0 is identity) ----
        if (__any_sync(0xffffffffu, (al0 < 1.f) || (al1 < 1.f))) {
#pragma unroll
            for (int jj = 0; jj < 16; jj++) {
                o[jj][0] *= al0; o[jj][1] *= al0;
                o[jj][2] *= al1; o[jj][3] *= al1;
            }
        }
        __syncwarp();

        // ---- O += P @ V (V fragments via LDS.64 pairs, conflict-free) ----
#pragma unroll
        for (int kk = 0; kk < 32; kk += 8) {
            uint32_t a0 = Ps[(wm + g) * SP + kk + t];
            uint32_t a1 = Ps[(wm + g + 8) * SP + kk + t];
            uint32_t a2 = Ps[(wm + g) * SP + kk + t + 4];
            uint32_t a3 = Ps[(wm + g + 8) * SP + kk + t + 4];
#pragma unroll
            for (int p = 0; p < 8; p++) {
                uint2 b0p = *(const uint2*)&Vc[(kk + t) * SV + p * 16 + 2 * g];
                uint2 b1p = *(const uint2*)&Vc[(kk + t + 4) * SV + p * 16 + 2 * g];
                mma8(o[2 * p],     a0, a1, a2, a3, b0p.x, b1p.x);
                mma8(o[2 * p + 1], a0, a1, a2, a3, b0p.y, b1p.y);
            }
        }
    }

    // ---- epilogue ----
    float inv0 = 1.f / l0, inv1 = 1.f / l1;
    int rlo = q0 + wm + g, rhi = rlo + 8;
    float* olo = out + ((size_t)b * TT + rlo) * HH;
    float* ohi = out + ((size_t)b * TT + rhi) * HH;
#pragma unroll
    for (int jj = 0; jj < 16; jj++) {
        int c = jj * 8 + 2 * t;
        float2 v0 = make_float2(o[jj][0] * inv0, o[jj][1] * inv0);
        float2 v1 = make_float2(o[jj][2] * inv1, o[jj][3] * inv1);
        *(float2*)&olo[c] = v0;
        *(float2*)&ohi[c] = v1;
    }
}

// ---------------------------------------------------------------------------
extern "C" void kernel_launch(void* const* d_in, const int* in_sizes, int n_in,
                              void* d_out, int out_size)
{
    const float* x  = (const float*)d_in[0];
    const float* Wk = (const float*)d_in[1];
    const float* Wq = (const float*)d_in[2];
    const float* Wv = (const float*)d_in[3];
    float* out = (float*)d_out;

    (void)in_sizes; (void)n_in; (void)out_size;

    const int proj_smem = (2 * PXS + 2 * PWS) * 4;   // 71680 (>= 128*132*4 staging)
    cudaFuncSetAttribute(proj_kernel,
                         cudaFuncAttributeMaxDynamicSharedMemorySize,
                         proj_smem);
    dim3 pgrid((BB * TT) / 128, 3);
    proj_kernel<<<pgrid, 256, proj_smem>>>(x, Wk, Wq, Wv);

    const int attn_smem = (2 * KBUF + 2 * VBUF + 64 * SP) * 4;  // 78848
    cudaFuncSetAttribute(attn_kernel,
                         cudaFuncAttributeMaxDynamicSharedMemorySize,
                         attn_smem);
    attn_kernel<<<BB * NQT, 128, attn_smem>>>(out);
}